// round 15
// baseline (speedup 1.0000x reference)
#include <cuda_runtime.h>
#include <cstdint>

// GRU-GNN fused kernel for GB300 (sm_103a), v5.
//   red[dst[e]] = h[src[e]]  (exactly one incoming edge per node)
//   gi = x @ w_ih^T + b_ih ; gh = red @ w_hh^T + b_hh
//   r=sig(i_r+h_r); z=sig(i_z+h_z); n=tanh(i_n + r*h_n); out=(1-z)n + z*red
//
// v5 vs v4 (2625us): crossbar law validated (4 cyc per LDS.128; v4's 2048
// LDS/item = 8192 cyc matched L1 time within 1%). Minimize per-step LDS
// R+3C under RC=16: R=8 rows x C=2 cols -> 14 LDS : 96 FFMA2 per warp-step
// (v4: 16). Lanes: tx(8 col groups) x gs(gate half) x kz(k half) in lane,
// ty = warp id (8 warps x 8 rows). kz-combine = shfl xor 16, gate
// exchange = xor 8; each thread keeps col tx+8*gs, sends the other.

#define MTILE 64            // edges (rows) per tile
#define CTILE 16            // output columns per tile
#define SP    132           // row stride in floats (split k: [0,64)+[68,132))
#define KO    68            // float offset of the k>=64 half within a row
#define WGS   (CTILE*SP+16) // 2128: gate-block stride (pad -> gs phases disjoint)
#define NTHREADS 256
#define GRID 152

#define WS_FLOATS (6 * WGS)          // 12768
#define XS_FLOATS (2 * MTILE * SP)   // 16896 per double-buffered array
// RS offset by +16 floats so x vs red lanes hit disjoint banks in a phase
#define SMEM_BYTES ((WS_FLOATS + 2 * XS_FLOATS + 16) * 4 + 6 * MTILE * 4)

__device__ __forceinline__ void fma2(unsigned long long& a,
                                     unsigned long long b,
                                     unsigned long long c) {
    // packed f32x2 FMA: a.lo += b.lo*c.lo ; a.hi += b.hi*c.hi  (SASS FFMA2)
    asm("fma.rn.f32x2 %0, %1, %2, %0;" : "+l"(a) : "l"(b), "l"(c));
}

__device__ __forceinline__ float sum2(unsigned long long v) {
    float lo = __uint_as_float((unsigned)(v & 0xffffffffull));
    float hi = __uint_as_float((unsigned)(v >> 32));
    return lo + hi;
}

__device__ __forceinline__ float sigmoid_f(float t) {
    return __fdividef(1.0f, 1.0f + __expf(-t));
}

__device__ __forceinline__ void cp16(void* s, const void* g) {
    unsigned sa = (unsigned)__cvta_generic_to_shared(s);
    asm volatile("cp.async.cg.shared.global [%0], [%1], 16;" :: "r"(sa), "l"(g));
}
#define CP_COMMIT() asm volatile("cp.async.commit_group;")
#define CP_WAIT0()  asm volatile("cp.async.wait_group 0;")

// split-row float offset for float4 chunk kq (0..31): [0,64) then [68,132)
__device__ __forceinline__ int fo4(int kq) { return 4 * kq + ((kq >= 16) ? 4 : 0); }

// cp.async one (x, red) row tile: 64 rows x 512B x 2 arrays, split-row layout
__device__ __forceinline__ void issue_tile(float* XS, float* RS,
                                           const int* IDXN, const int* IDXS,
                                           const float* __restrict__ x,
                                           const float* __restrict__ h,
                                           int buf, int slot, int t) {
#pragma unroll
    for (int j = 0; j < 8; j++) {
        int f   = t + NTHREADS * j;      // 0..2047
        int row = f >> 5;                // 0..63
        int kq  = f & 31;                // float4 index along k
        int fo  = fo4(kq);
        int node = IDXN[slot * MTILE + row];
        int s    = IDXS[slot * MTILE + row];
        cp16(XS + (buf * MTILE + row) * SP + fo, x + (size_t)node * 128 + 4 * kq);
        cp16(RS + (buf * MTILE + row) * SP + fo, h + (size_t)s    * 128 + 4 * kq);
    }
}

__global__ void __launch_bounds__(NTHREADS, 1)
gru_gnn_v5_kernel(const float* __restrict__ x, const float* __restrict__ h,
                  const float* __restrict__ w_ih, const float* __restrict__ w_hh,
                  const float* __restrict__ b_ih, const float* __restrict__ b_hh,
                  const int* __restrict__ src, const int* __restrict__ dst,
                  float* __restrict__ out, int N, int num_mt, int total)
{
    extern __shared__ __align__(16) char smem_raw[];
    float* WS = (float*)smem_raw;              // weights [6][WGS] gate-padded
    float* XS = WS + WS_FLOATS;                // x tiles  [2][MTILE][SP]
    float* RS = XS + XS_FLOATS + 16;           // red tiles (bank-offset +16)
    int* IDXN = (int*)(RS + XS_FLOATS);        // [3][MTILE] output node per row
    int* IDXS = IDXN + 3 * MTILE;              // [3][MTILE] gather src per row

    const int t  = threadIdx.x;
    const int tx = t & 7;          // col group: computes cols tx, tx+8
    const int gs = (t >> 3) & 1;   // 0: ih gates (x), 1: hh gates (red)
    const int kz = (t >> 4) & 1;   // k-half: [0,64) or [64,128)
    const int ty = t >> 5;         // warp id 0..7 -> rows 8*ty .. 8*ty+7
    const int G  = gridDim.x;

    int it0 = blockIdx.x;
    if (it0 >= total) return;

    // ---------------- prologue ----------------
    {
        int mt = it0 % num_mt;
        if (t < MTILE) {
            int e = mt * MTILE + t; if (e >= N) e = N - 1;
            IDXN[t] = dst[e];
            IDXS[t] = src[e];
        }
    }
    __syncthreads();
    issue_tile(XS, RS, IDXN, IDXS, x, h, /*buf=*/0, /*slot=*/0, t);
    CP_COMMIT();
    if (it0 + G < total) {
        int mt = (it0 + G) % num_mt;
        if (t < MTILE) {
            int e = mt * MTILE + t; if (e >= N) e = N - 1;
            IDXN[MTILE + t] = dst[e];
            IDXS[MTILE + t] = src[e];
        }
    }

    const int kept = gs;           // ci this thread outputs (col tx + 8*gs)
    const int comp = 1 - gs;       // ci sent to the gs partner
    int cur_ct = -1;
    float bi0 = 0.f, bi1 = 0.f, bi2 = 0.f, bh0 = 0.f, bh1 = 0.f, bh2 = 0.f;

    // ---------------- main loop over work items (ct-major) ----------------
    for (int n = 0;; n++) {
        int it = it0 + n * G;
        if (it >= total) break;
        int buf  = n & 1;
        int slot = n % 3;
        int ct = it / num_mt;            // column tile (changes rarely)

        CP_WAIT0();                      // this tile's x/red copies retired
        __syncthreads();                 // ...visible to all; prior iter done

        bool wload = (ct != cur_ct);
        if (wload) {
            int c0 = ct * CTILE;
#pragma unroll
            for (int i = 0; i < 12; i++) {
                int f = t + NTHREADS * i;        // 3072 float4s = 6*16*32
                int rowf = f >> 5, kq = f & 31;
                int g = rowf >> 4, c = rowf & 15;
                const float* base = (g < 3) ? w_ih : w_hh;
                int g3 = (g < 3) ? g : g - 3;
                float4 v = *(const float4*)(base + ((size_t)(g3 * 128 + c0 + c)) * 128 + 4 * kq);
                *(float4*)(WS + g * WGS + c * SP + fo4(kq)) = v;
            }
            int cg = c0 + tx + 8 * gs;
            bi0 = b_ih[cg];       bh0 = b_hh[cg];
            bi1 = b_ih[cg + 128]; bh1 = b_hh[cg + 128];
            bi2 = b_ih[cg + 256]; bh2 = b_hh[cg + 256];
            cur_ct = ct;
        }

        // prefetch next tile into the other buffer (overlaps compute)
        if (it + G < total) {
            issue_tile(XS, RS, IDXN, IDXS, x, h, buf ^ 1, (n + 1) % 3, t);
            CP_COMMIT();
        }
        // indices two tiles ahead (slot (n+2)%3: not read until next iter)
        if (it + 2 * G < total) {
            int mt2 = (it + 2 * G) % num_mt;
            int sl2 = (n + 2) % 3;
            if (t < MTILE) {
                int e = mt2 * MTILE + t; if (e >= N) e = N - 1;
                IDXN[sl2 * MTILE + t] = dst[e];
                IDXS[sl2 * MTILE + t] = src[e];
            }
        }
        if (wload) __syncthreads();      // weights visible before compute

        // ---- compute: 3 gates x 8 rows x 2 cols over this (gs, kz) part ----
        unsigned long long acc[3][8][2];
#pragma unroll
        for (int j = 0; j < 3; j++)
#pragma unroll
            for (int r = 0; r < 8; r++)
#pragma unroll
                for (int ci = 0; ci < 2; ci++) acc[j][r][ci] = 0ull;

        const float* ab = (gs ? RS : XS) + (buf * MTILE + 8 * ty) * SP + kz * KO;
        const float* wb = WS + 3 * gs * WGS + tx * SP + kz * KO;

#pragma unroll 2
        for (int k = 0; k < 64; k += 4) {
            ulonglong2 av[8];
#pragma unroll
            for (int r = 0; r < 8; r++)
                av[r] = *(const ulonglong2*)(ab + r * SP + k);
#pragma unroll
            for (int j = 0; j < 3; j++) {
#pragma unroll
                for (int ci = 0; ci < 2; ci++) {
                    ulonglong2 wv = *(const ulonglong2*)(
                        wb + j * WGS + 8 * ci * SP + k);
#pragma unroll
                    for (int r = 0; r < 8; r++) {
                        fma2(acc[j][r][ci], wv.x, av[r].x);
                        fma2(acc[j][r][ci], wv.y, av[r].y);
                    }
                }
            }
        }

        // ---- combine kz halves (48 shfl), exchange gate halves (12 shfl) ----
        float fsum[3][8][2];
#pragma unroll
        for (int j = 0; j < 3; j++)
#pragma unroll
            for (int r = 0; r < 8; r++)
#pragma unroll
                for (int ci = 0; ci < 2; ci++) {
                    float p = sum2(acc[j][r][ci]);
                    fsum[j][r][ci] = p + __shfl_xor_sync(0xffffffffu, p, 16);
                }

        float oth[3][4];       // partner's gate triple for my col, 4 rows
#pragma unroll
        for (int j = 0; j < 3; j++)
#pragma unroll
            for (int r2 = 0; r2 < 4; r2++)
                oth[j][r2] = __shfl_xor_sync(
                    0xffffffffu, fsum[j][4 * kz + r2][comp], 8);

        // ---- GRU epilogue: 4 rows (kz-split) x 1 col per thread ----
        int c0 = ct * CTILE;
        int cg = c0 + tx + 8 * gs;
        int co = cg + ((cg >= 64) ? 4 : 0);   // split-row offset of element cg
#pragma unroll
        for (int r2 = 0; r2 < 4; r2++) {
            int r    = 4 * kz + r2;
            int row  = 8 * ty + r;
            int node = IDXN[slot * MTILE + row];
            float a0 = fsum[0][r][kept];
            float a1 = fsum[1][r][kept];
            float a2 = fsum[2][r][kept];
            float o0 = oth[0][r2], o1 = oth[1][r2], o2 = oth[2][r2];
            float gr = gs ? o0 : a0, hr = gs ? a0 : o0;
            float gz = gs ? o1 : a1, hz = gs ? a1 : o1;
            float gn = gs ? o2 : a2, hn = gs ? a2 : o2;
            float rg = sigmoid_f((gr + bi0) + (hr + bh0));
            float zg = sigmoid_f((gz + bi1) + (hz + bh1));
            float ng = tanhf((gn + bi2) + rg * (hn + bh2));
            float red = RS[(buf * MTILE + row) * SP + co];
            out[(size_t)node * 128 + cg] = (1.0f - zg) * ng + zg * red;
        }
    }
}

extern "C" void kernel_launch(void* const* d_in, const int* in_sizes, int n_in,
                              void* d_out, int out_size) {
    const float* x    = (const float*)d_in[0];
    const float* h    = (const float*)d_in[1];
    const float* w_ih = (const float*)d_in[2];
    const float* w_hh = (const float*)d_in[3];
    const float* b_ih = (const float*)d_in[4];
    const float* b_hh = (const float*)d_in[5];
    const int*   src  = (const int*)d_in[6];
    const int*   dst  = (const int*)d_in[7];
    float* out = (float*)d_out;

    int N = in_sizes[6];                 // #edges == #nodes
    int num_mt = (N + MTILE - 1) / MTILE;
    int total  = (128 / CTILE) * num_mt; // 8 column tiles

    cudaFuncSetAttribute(gru_gnn_v5_kernel,
                         cudaFuncAttributeMaxDynamicSharedMemorySize, SMEM_BYTES);

    int grid = GRID < total ? GRID : total;
    gru_gnn_v5_kernel<<<grid, NTHREADS, SMEM_BYTES>>>(
        x, h, w_ih, w_hh, b_ih, b_hh, src, dst, out, N, num_mt, total);
}